// round 5
// baseline (speedup 1.0000x reference)
#include <cuda_runtime.h>
#include <cstdint>

// ---------------------------------------------------------------------------
// Problem constants
// ---------------------------------------------------------------------------
#define BATCH 2
#define H0 192
#define W0 192
#define HQ 96
#define WQ 96
#define LQ (HQ * WQ)        // 9216
#define HK 48
#define WK 48
#define LK (HK * WK)        // 2304
#define KF 144              // 16 channels * 9 patch positions

typedef unsigned long long u64;

// Packed f32x2 helpers (sm_100+): 2 IEEE fp32 FMAs per issue slot.
__device__ __forceinline__ u64 pack2(float lo, float hi) {
    u64 r;
    asm("mov.b64 %0, {%1, %2};" : "=l"(r) : "f"(lo), "f"(hi));
    return r;
}
__device__ __forceinline__ u64 fma2(u64 a, u64 b, u64 c) {
    u64 d;
    asm("fma.rn.f32x2 %0, %1, %2, %3;" : "=l"(d) : "l"(a), "l"(b), "l"(c));
    return d;
}
__device__ __forceinline__ void unpack2(u64 v, float& lo, float& hi) {
    asm("mov.b64 {%0, %1}, %2;" : "=f"(lo), "=f"(hi) : "l"(v));
}

// ---------------------------------------------------------------------------
// Scratch buffers (device globals; no allocation allowed)
// ---------------------------------------------------------------------------
__device__ float g_qc1[BATCH * 64 * H0 * W0];
__device__ float g_qc2[BATCH * 64 * H0 * W0];
__device__ float g_qp [BATCH * 64 * HQ * WQ];
__device__ float g_qc3[BATCH * 128 * HQ * WQ];
__device__ float g_qf [BATCH * 16 * HQ * WQ];

__device__ float g_kin[BATCH * 3 * HQ * WQ];
__device__ float g_kc1[BATCH * 64 * HQ * WQ];
__device__ float g_kc2[BATCH * 64 * HQ * WQ];
__device__ float g_kp [BATCH * 64 * HK * WK];
__device__ float g_kc3[BATCH * 128 * HK * WK];
__device__ float g_kf [BATCH * 16 * HK * WK];

__device__ float g_qn [BATCH * KF * LQ];   // normalized query patches [B][144][Lq]
__device__ float g_kn [BATCH * LK * KF];   // normalized key patches   [B][Lk][144]

// ---------------------------------------------------------------------------
// conv3x3 (zero pad 1) + ReLU.
// Block: 16x16 threads; 4 wide x 2 tall microtile x 8 oc -> 64x32 tile.
// Two input channels per shared-memory phase.
// ---------------------------------------------------------------------------
#define CTW 64
#define CTH 32
#define SIN_H (CTH + 2)               // 34
#define SIN_W (CTW + 4)               // 68
#define TILE_ELEMS ((CTH + 2) * (CTW + 2))   // 34*66 = 2244

__global__ void __launch_bounds__(256) conv3x3_relu(
    const float* __restrict__ in, const float* __restrict__ w,
    const float* __restrict__ bias, float* __restrict__ out,
    int Cin, int Cout, int H, int W) {

    __shared__ float s_in[2][SIN_H][SIN_W];
    __shared__ float s_w[2][8][9];

    const int nOcB = Cout >> 3;
    const int b    = blockIdx.z / nOcB;
    const int ocb  = blockIdx.z % nOcB;
    const int x0   = blockIdx.x * CTW;
    const int y0   = blockIdx.y * CTH;
    const int tx   = threadIdx.x;              // 0..15
    const int ty   = threadIdx.y;              // 0..15
    const int tid  = ty * 16 + tx;
    const int px   = tx * 4;
    const int py   = ty * 2;

    float acc[8][2][4];
#pragma unroll
    for (int i = 0; i < 8; i++)
#pragma unroll
        for (int r = 0; r < 2; r++)
#pragma unroll
            for (int p = 0; p < 4; p++) acc[i][r][p] = 0.f;

    const float* inB = in + (size_t)b * Cin * H * W;
    const float* wB  = w + (size_t)(ocb * 8) * Cin * 9;

    const int cinPairs = Cin & ~1;

    for (int ci0 = 0; ci0 < cinPairs; ci0 += 2) {
        for (int i = tid; i < 2 * TILE_ELEMS; i += 256) {
            int ch = i / TILE_ELEMS;
            int e  = i % TILE_ELEMS;
            int r  = e / (CTW + 2);
            int c  = e % (CTW + 2);
            int gy = y0 + r - 1;
            int gx = x0 + c - 1;
            float v = 0.f;
            if (gy >= 0 && gy < H && gx >= 0 && gx < W)
                v = inB[((size_t)(ci0 + ch) * H + gy) * W + gx];
            s_in[ch][r][c] = v;
        }
        if (tid < 144) {
            int ch = tid / 72;
            int rr = tid % 72;
            int oc = rr / 9;
            int k  = rr % 9;
            s_w[ch][oc][k] = wB[((size_t)oc * Cin + ci0 + ch) * 9 + k];
        }
        __syncthreads();

#pragma unroll
        for (int ch = 0; ch < 2; ch++) {
            float v[4][6];
#pragma unroll
            for (int dy = 0; dy < 4; dy++)
#pragma unroll
                for (int c = 0; c < 6; c++)
                    v[dy][c] = s_in[ch][py + dy][px + c];

#pragma unroll
            for (int oc = 0; oc < 8; oc++) {
                float w0 = s_w[ch][oc][0], w1 = s_w[ch][oc][1], w2 = s_w[ch][oc][2];
                float w3 = s_w[ch][oc][3], w4 = s_w[ch][oc][4], w5 = s_w[ch][oc][5];
                float w6 = s_w[ch][oc][6], w7 = s_w[ch][oc][7], w8 = s_w[ch][oc][8];
#pragma unroll
                for (int r = 0; r < 2; r++) {
#pragma unroll
                    for (int p = 0; p < 4; p++) {
                        float a = acc[oc][r][p];
                        a = fmaf(v[r + 0][p], w0, a);
                        a = fmaf(v[r + 0][p + 1], w1, a);
                        a = fmaf(v[r + 0][p + 2], w2, a);
                        a = fmaf(v[r + 1][p], w3, a);
                        a = fmaf(v[r + 1][p + 1], w4, a);
                        a = fmaf(v[r + 1][p + 2], w5, a);
                        a = fmaf(v[r + 2][p], w6, a);
                        a = fmaf(v[r + 2][p + 1], w7, a);
                        a = fmaf(v[r + 2][p + 2], w8, a);
                        acc[oc][r][p] = a;
                    }
                }
            }
        }
        __syncthreads();
    }

    if (Cin & 1) {
        int ci = Cin - 1;
        for (int i = tid; i < TILE_ELEMS; i += 256) {
            int r  = i / (CTW + 2);
            int c  = i % (CTW + 2);
            int gy = y0 + r - 1;
            int gx = x0 + c - 1;
            float v = 0.f;
            if (gy >= 0 && gy < H && gx >= 0 && gx < W)
                v = inB[((size_t)ci * H + gy) * W + gx];
            s_in[0][r][c] = v;
        }
        if (tid < 72) {
            int oc = tid / 9;
            int k  = tid % 9;
            s_w[0][oc][k] = wB[((size_t)oc * Cin + ci) * 9 + k];
        }
        __syncthreads();

        float v[4][6];
#pragma unroll
        for (int dy = 0; dy < 4; dy++)
#pragma unroll
            for (int c = 0; c < 6; c++)
                v[dy][c] = s_in[0][py + dy][px + c];

#pragma unroll
        for (int oc = 0; oc < 8; oc++) {
            float w0 = s_w[0][oc][0], w1 = s_w[0][oc][1], w2 = s_w[0][oc][2];
            float w3 = s_w[0][oc][3], w4 = s_w[0][oc][4], w5 = s_w[0][oc][5];
            float w6 = s_w[0][oc][6], w7 = s_w[0][oc][7], w8 = s_w[0][oc][8];
#pragma unroll
            for (int r = 0; r < 2; r++) {
#pragma unroll
                for (int p = 0; p < 4; p++) {
                    float a = acc[oc][r][p];
                    a = fmaf(v[r + 0][p], w0, a);
                    a = fmaf(v[r + 0][p + 1], w1, a);
                    a = fmaf(v[r + 0][p + 2], w2, a);
                    a = fmaf(v[r + 1][p], w3, a);
                    a = fmaf(v[r + 1][p + 1], w4, a);
                    a = fmaf(v[r + 1][p + 2], w5, a);
                    a = fmaf(v[r + 2][p], w6, a);
                    a = fmaf(v[r + 2][p + 1], w7, a);
                    a = fmaf(v[r + 2][p + 2], w8, a);
                    acc[oc][r][p] = a;
                }
            }
        }
        __syncthreads();
    }

    const int xbase = x0 + px;
#pragma unroll
    for (int r = 0; r < 2; r++) {
        const int y = y0 + py + r;
        if (y >= H) continue;
#pragma unroll
        for (int oc = 0; oc < 8; oc++) {
            float bv = bias[ocb * 8 + oc];
            float* orow = out + (((size_t)b * Cout + ocb * 8 + oc) * H + y) * W;
            if (xbase + 3 < W) {
                float4 rr;
                rr.x = fmaxf(acc[oc][r][0] + bv, 0.f);
                rr.y = fmaxf(acc[oc][r][1] + bv, 0.f);
                rr.z = fmaxf(acc[oc][r][2] + bv, 0.f);
                rr.w = fmaxf(acc[oc][r][3] + bv, 0.f);
                *(float4*)(orow + xbase) = rr;
            } else {
#pragma unroll
                for (int p = 0; p < 4; p++) {
                    if (xbase + p < W)
                        orow[xbase + p] = fmaxf(acc[oc][r][p] + bv, 0.f);
                }
            }
        }
    }
}

// ---------------------------------------------------------------------------
// 2x2 pooling kernels. BC = B*C combined channel count.
// ---------------------------------------------------------------------------
__global__ void maxpool2_kernel(const float* __restrict__ in, float* __restrict__ out,
                                int BC, int H, int W) {
    int Ho = H >> 1, Wo = W >> 1;
    int idx = blockIdx.x * blockDim.x + threadIdx.x;
    if (idx >= BC * Ho * Wo) return;
    int x = idx % Wo;
    int y = (idx / Wo) % Ho;
    int c = idx / (Wo * Ho);
    const float* p = in + ((size_t)c * H + 2 * y) * W + 2 * x;
    out[idx] = fmaxf(fmaxf(p[0], p[1]), fmaxf(p[W], p[W + 1]));
}

__global__ void avgpool2_kernel(const float* __restrict__ in, float* __restrict__ out,
                                int BC, int H, int W) {
    int Ho = H >> 1, Wo = W >> 1;
    int idx = blockIdx.x * blockDim.x + threadIdx.x;
    if (idx >= BC * Ho * Wo) return;
    int x = idx % Wo;
    int y = (idx / Wo) % Ho;
    int c = idx / (Wo * Ho);
    const float* p = in + ((size_t)c * H + 2 * y) * W + 2 * x;
    out[idx] = 0.25f * (p[0] + p[1] + p[W] + p[W + 1]);
}

// ---------------------------------------------------------------------------
// conv1x1 (128 -> 16) + LeakyReLU(0.2). Thread per pixel, 16 accumulators.
// ---------------------------------------------------------------------------
__global__ void conv1x1_lrelu(const float* __restrict__ in, const float* __restrict__ w,
                              const float* __restrict__ bias, float* __restrict__ out,
                              int Cin, int HW, int B) {
    __shared__ float s_w[128 * 16];   // [ci][oc]
    __shared__ float s_b[16];
    int tid = threadIdx.x;
    for (int i = tid; i < Cin * 16; i += blockDim.x) {
        int ci = i / 16, oc = i % 16;
        s_w[i] = w[(size_t)oc * Cin + ci];
    }
    if (tid < 16) s_b[tid] = bias[tid];
    __syncthreads();

    int p = blockIdx.x * blockDim.x + tid;
    if (p >= B * HW) return;
    int b   = p / HW;
    int pix = p % HW;
    const float* ib = in + (size_t)b * Cin * HW + pix;

    float acc[16];
#pragma unroll
    for (int oc = 0; oc < 16; oc++) acc[oc] = 0.f;

    for (int ci = 0; ci < Cin; ci++) {
        float v = ib[(size_t)ci * HW];
#pragma unroll
        for (int oc = 0; oc < 16; oc++) acc[oc] = fmaf(v, s_w[ci * 16 + oc], acc[oc]);
    }
#pragma unroll
    for (int oc = 0; oc < 16; oc++) {
        float r = acc[oc] + s_b[oc];
        out[((size_t)b * 16 + oc) * HW + pix] = (r > 0.f) ? r : 0.2f * r;
    }
}

// ---------------------------------------------------------------------------
// Unfold 3x3 (reflect pad 1) + L2 normalize.
// ---------------------------------------------------------------------------
__device__ __forceinline__ int reflect_idx(int v, int n) {
    if (v < 0) v = -v;
    if (v >= n) v = 2 * n - 2 - v;
    return v;
}

// Query: output layout [B][144][Lq] (query index contiguous).
__global__ void unfold_norm_q(const float* __restrict__ f, float* __restrict__ outT) {
    int lq = blockIdx.x * blockDim.x + threadIdx.x;
    int b  = blockIdx.y;
    if (lq >= LQ) return;
    int y = lq / WQ, x = lq % WQ;
    const float* fb = f + (size_t)b * 16 * LQ;
    float* ob = outT + (size_t)b * KF * LQ;

    float vals[KF];
    float s = 0.f;
#pragma unroll
    for (int c = 0; c < 16; c++) {
#pragma unroll
        for (int dy = -1; dy <= 1; dy++) {
#pragma unroll
            for (int dx = -1; dx <= 1; dx++) {
                int yy = reflect_idx(y + dy, HQ);
                int xx = reflect_idx(x + dx, WQ);
                float v = fb[c * LQ + yy * WQ + xx];
                vals[c * 9 + (dy + 1) * 3 + (dx + 1)] = v;
                s += v * v;
            }
        }
    }
    float inv = 1.f / fmaxf(sqrtf(s), 1e-12f);
#pragma unroll
    for (int fi = 0; fi < KF; fi++) ob[(size_t)fi * LQ + lq] = vals[fi] * inv;
}

// Key: output layout [B][Lk][144] (feature contiguous per key patch).
__global__ void unfold_norm_k(const float* __restrict__ f, float* __restrict__ outR) {
    int lk = blockIdx.x * blockDim.x + threadIdx.x;
    int b  = blockIdx.y;
    if (lk >= LK) return;
    int y = lk / WK, x = lk % WK;
    const float* fb = f + (size_t)b * 16 * LK;
    float* ob = outR + ((size_t)b * LK + lk) * KF;

    float vals[KF];
    float s = 0.f;
#pragma unroll
    for (int c = 0; c < 16; c++) {
#pragma unroll
        for (int dy = -1; dy <= 1; dy++) {
#pragma unroll
            for (int dx = -1; dx <= 1; dx++) {
                int yy = reflect_idx(y + dy, HK);
                int xx = reflect_idx(x + dx, WK);
                float v = fb[c * LK + yy * WK + xx];
                vals[c * 9 + (dy + 1) * 3 + (dx + 1)] = v;
                s += v * v;
            }
        }
    }
    float inv = 1.f / fmaxf(sqrtf(s), 1e-12f);
#pragma unroll
    for (int fi = 0; fi < KF; fi++) ob[fi] = vals[fi] * inv;
}

// ---------------------------------------------------------------------------
// Fused cosine-similarity GEMM + max/argmax over keys, with packed f32x2 FMA.
// A = g_kn [B][LK][144] (K contiguous), Bm = g_qn [B][144][LQ] (Lq contiguous).
// Query panel [144][128] resident in smem; key tiles double-buffered.
// Microtile: 8 keys x 4 query-PAIRS per thread (fma.rn.f32x2).
// grid.x = LQ/128 = 72, grid.y = B.
// ---------------------------------------------------------------------------
#define NKC (KF / 8)                 // 18 k-chunks
#define GEMM_BQ_ELEMS (KF * 128)     // 18432 floats
#define GEMM_AS_ELEMS (2 * 8 * 132)  // 2112 floats
#define GEMM_RV_ELEMS (16 * 128)     // 2048 floats
#define GEMM_RI_ELEMS (16 * 128)     // 2048 ints
#define GEMM_SMEM_BYTES ((GEMM_BQ_ELEMS + GEMM_AS_ELEMS + GEMM_RV_ELEMS + GEMM_RI_ELEMS) * 4)

__global__ void __launch_bounds__(256) simgemm_maxidx(
    const float* __restrict__ A, const float* __restrict__ Bm,
    float* __restrict__ outMap, float* __restrict__ outIdx) {

    extern __shared__ float smem[];
    float (*Bq)[128]    = (float (*)[128])smem;                       // [144][128]
    float (*As)[8][132] = (float (*)[8][132])(smem + GEMM_BQ_ELEMS);  // [2][8][132]
    float (*rv)[128]    = (float (*)[128])(smem + GEMM_BQ_ELEMS + GEMM_AS_ELEMS);
    int   (*ri)[128]    = (int (*)[128])(smem + GEMM_BQ_ELEMS + GEMM_AS_ELEMS + GEMM_RV_ELEMS);

    const int b   = blockIdx.y;
    const int qn0 = blockIdx.x * 128;
    const int tid = threadIdx.x;
    const int txq = tid % 16;      // query group (8 queries = 4 pairs)
    const int tyk = tid / 16;      // key group (8 keys)

    const float* Ab = A  + (size_t)b * LK * KF;
    const float* Bb = Bm + (size_t)b * KF * LQ;

    // Load the full query panel once: [144][128], float4 coalesced.
    for (int i = tid * 4; i < GEMM_BQ_ELEMS; i += 256 * 4) {
        int k = i >> 7;
        int q = i & 127;
        *(float4*)&Bq[k][q] = *(const float4*)(Bb + (size_t)k * LQ + qn0 + q);
    }

    float rmax[8];
    int   ridx[8];
#pragma unroll
    for (int j = 0; j < 8; j++) { rmax[j] = -1e30f; ridx[j] = 0; }

    const int am  = tid >> 1;
    const int akk = (tid & 1) * 4;

    for (int km0 = 0; km0 < LK; km0 += 128) {
        u64 acc2[8][4];   // [key][query-pair]
#pragma unroll
        for (int i = 0; i < 8; i++)
#pragma unroll
            for (int j = 0; j < 4; j++) acc2[i][j] = 0ull;

        // preload chunk 0 into buffer 0
        {
            const float4 av = *(const float4*)(Ab + (size_t)(km0 + am) * KF + akk);
            As[0][akk + 0][am] = av.x;
            As[0][akk + 1][am] = av.y;
            As[0][akk + 2][am] = av.z;
            As[0][akk + 3][am] = av.w;
        }
        __syncthreads();

        for (int t = 0; t < NKC; t++) {
            int buf = t & 1;
            if (t + 1 < NKC) {
                int nbuf = buf ^ 1;
                const float4 av = *(const float4*)(Ab + (size_t)(km0 + am) * KF + (t + 1) * 8 + akk);
                As[nbuf][akk + 0][am] = av.x;
                As[nbuf][akk + 1][am] = av.y;
                As[nbuf][akk + 2][am] = av.z;
                As[nbuf][akk + 3][am] = av.w;
            }
            const int k0 = t * 8;
#pragma unroll
            for (int k = 0; k < 8; k++) {
                // 4 query pairs via natural LDS.64 (txq*8 is even -> 8B aligned)
                u64 bf2[4];
#pragma unroll
                for (int j = 0; j < 4; j++)
                    bf2[j] = *(const u64*)&Bq[k0 + k][txq * 8 + 2 * j];
                // 8 key scalars splatted into pairs
#pragma unroll
                for (int i = 0; i < 8; i++) {
                    float af = As[buf][k][tyk * 8 + i];
                    u64 av2 = pack2(af, af);
#pragma unroll
                    for (int j = 0; j < 4; j++)
                        acc2[i][j] = fma2(av2, bf2[j], acc2[i][j]);
                }
            }
            __syncthreads();
        }

        // running max/argmax (keys ascending: strict > keeps first occurrence)
#pragma unroll
        for (int i = 0; i < 8; i++) {
#pragma unroll
            for (int j = 0; j < 4; j++) {
                float vlo, vhi;
                unpack2(acc2[i][j], vlo, vhi);
                int jl = 2 * j, jh = 2 * j + 1;
                if (vlo > rmax[jl]) { rmax[jl] = vlo; ridx[jl] = km0 + tyk * 8 + i; }
                if (vhi > rmax[jh]) { rmax[jh] = vhi; ridx[jh] = km0 + tyk * 8 + i; }
            }
        }
    }

    // Cross-thread reduction over the 16 key groups per query.
#pragma unroll
    for (int j = 0; j < 8; j++) {
        rv[tyk][txq * 8 + j] = rmax[j];
        ri[tyk][txq * 8 + j] = ridx[j];
    }
    __syncthreads();

    if (tid < 128) {
        float bv = rv[0][tid];
        int   bi = ri[0][tid];
#pragma unroll
        for (int t = 1; t < 16; t++) {
            float v   = rv[t][tid];
            int   idx = ri[t][tid];
            if (v > bv || (v == bv && idx < bi)) { bv = v; bi = idx; }
        }
        outMap[(size_t)b * LQ + qn0 + tid] = bv;
        outIdx[(size_t)b * LQ + qn0 + tid] = (float)bi;
    }
}

// ---------------------------------------------------------------------------
// Launch
// ---------------------------------------------------------------------------
extern "C" void kernel_launch(void* const* d_in, const int* in_sizes, int n_in,
                              void* d_out, int out_size) {
    const float* query = (const float*)d_in[0];
    const float* key   = (const float*)d_in[1];
    const float* w1 = (const float*)d_in[2];
    const float* b1 = (const float*)d_in[3];
    const float* w2 = (const float*)d_in[4];
    const float* b2 = (const float*)d_in[5];
    const float* w3 = (const float*)d_in[6];
    const float* b3 = (const float*)d_in[7];
    const float* wm = (const float*)d_in[8];
    const float* bm = (const float*)d_in[9];
    // d_in[10] = flag_8k (truthy -> no bicubic branches)

    float* out = (float*)d_out;
    float* outMap = out;              // [B][Lq] relevance maps
    float* outIdx = out + BATCH * LQ; // [B][Lq] hard indices (as float)

    float* qc1; cudaGetSymbolAddress((void**)&qc1, g_qc1);
    float* qc2; cudaGetSymbolAddress((void**)&qc2, g_qc2);
    float* qp;  cudaGetSymbolAddress((void**)&qp,  g_qp);
    float* qc3; cudaGetSymbolAddress((void**)&qc3, g_qc3);
    float* qf;  cudaGetSymbolAddress((void**)&qf,  g_qf);
    float* kin; cudaGetSymbolAddress((void**)&kin, g_kin);
    float* kc1; cudaGetSymbolAddress((void**)&kc1, g_kc1);
    float* kc2; cudaGetSymbolAddress((void**)&kc2, g_kc2);
    float* kp;  cudaGetSymbolAddress((void**)&kp,  g_kp);
    float* kc3; cudaGetSymbolAddress((void**)&kc3, g_kc3);
    float* kf;  cudaGetSymbolAddress((void**)&kf,  g_kf);
    float* qn;  cudaGetSymbolAddress((void**)&qn,  g_qn);
    float* kn;  cudaGetSymbolAddress((void**)&kn,  g_kn);

    // Allow >48KB dynamic smem for the GEMM. Unconditional every call:
    // deterministic, idempotent, not a stream operation.
    cudaFuncSetAttribute(simgemm_maxidx,
                         cudaFuncAttributeMaxDynamicSharedMemorySize,
                         GEMM_SMEM_BYTES);

    dim3 blk(16, 16);

    // ---- Query branch: 192x192 ----
    conv3x3_relu<<<dim3(W0 / CTW, H0 / CTH, BATCH * 8), blk>>>(query, w1, b1, qc1, 3, 64, H0, W0);
    conv3x3_relu<<<dim3(W0 / CTW, H0 / CTH, BATCH * 8), blk>>>(qc1, w2, b2, qc2, 64, 64, H0, W0);
    {
        int total = BATCH * 64 * HQ * WQ;
        maxpool2_kernel<<<(total + 255) / 256, 256>>>(qc2, qp, BATCH * 64, H0, W0);
    }
    conv3x3_relu<<<dim3((WQ + CTW - 1) / CTW, (HQ + CTH - 1) / CTH, BATCH * 16), blk>>>(qp, w3, b3, qc3, 64, 128, HQ, WQ);
    conv1x1_lrelu<<<(BATCH * LQ + 255) / 256, 256>>>(qc3, wm, bm, qf, 128, LQ, BATCH);
    unfold_norm_q<<<dim3((LQ + 255) / 256, BATCH), 256>>>(qf, qn);

    // ---- Key branch: avgpool to 96x96 then same stack ----
    {
        int total = BATCH * 3 * HQ * WQ;
        avgpool2_kernel<<<(total + 255) / 256, 256>>>(key, kin, BATCH * 3, H0, W0);
    }
    conv3x3_relu<<<dim3((WQ + CTW - 1) / CTW, (HQ + CTH - 1) / CTH, BATCH * 8), blk>>>(kin, w1, b1, kc1, 3, 64, HQ, WQ);
    conv3x3_relu<<<dim3((WQ + CTW - 1) / CTW, (HQ + CTH - 1) / CTH, BATCH * 8), blk>>>(kc1, w2, b2, kc2, 64, 64, HQ, WQ);
    {
        int total = BATCH * 64 * HK * WK;
        maxpool2_kernel<<<(total + 255) / 256, 256>>>(kc2, kp, BATCH * 64, HQ, WQ);
    }
    conv3x3_relu<<<dim3((WK + CTW - 1) / CTW, (HK + CTH - 1) / CTH, BATCH * 16), blk>>>(kp, w3, b3, kc3, 64, 128, HK, WK);
    conv1x1_lrelu<<<(BATCH * LK + 255) / 256, 256>>>(kc3, wm, bm, kf, 128, LK, BATCH);
    unfold_norm_k<<<dim3((LK + 255) / 256, BATCH), 256>>>(kf, kn);

    // ---- Cosine similarity GEMM + max/argmax ----
    simgemm_maxidx<<<dim3(LQ / 128, BATCH), 256, GEMM_SMEM_BYTES>>>(kn, qn, outMap, outIdx);
}